// round 3
// baseline (speedup 1.0000x reference)
#include <cuda_runtime.h>

#define NB   2
#define LQ   1024
#define LIN  4096
#define CC   256
#define MH   8
#define NP   4
#define SPTS (NB*LQ*MH*NP)   /* 65536 sampling points */

// ---------------- scratch (device globals; no allocation allowed) ----------
__device__ float g_value[NB*LIN*CC];   // (B, Lin, M, D) = 8 MiB
__device__ float g_loc[SPTS*3];        // sampling locations
__device__ float g_attw[SPTS];         // softmaxed attention weights
__device__ float g_bd[2][SPTS];        // per-half best distance
__device__ int   g_bi[2][SPTS];        // per-half best index (absolute)
__device__ float g_mid[NB*LQ*CC];      // pre-output-projection features

// ---------------- packed f32x2 helpers --------------------------------------
typedef unsigned long long u64;
__device__ __forceinline__ u64 pk2(float a, float b) {
    u64 r; asm("mov.b64 %0,{%1,%2};" : "=l"(r) : "f"(a), "f"(b)); return r;
}
__device__ __forceinline__ u64 ffma2(u64 a, u64 b, u64 c) {
    u64 d; asm("fma.rn.f32x2 %0,%1,%2,%3;" : "=l"(d) : "l"(a), "l"(b), "l"(c)); return d;
}
__device__ __forceinline__ float2 up2(u64 v) {
    float2 f; asm("mov.b64 {%0,%1},%2;" : "=f"(f.x), "=f"(f.y) : "l"(v)); return f;
}

// ---------------- tiled SGEMM-NT, K=256, BM=BN=64, BK=16, 256 thr, 4x4 ------
// Out[r,c] = sum_k A[r,k] * Wrow(c)[k] + bias(c)
// Weight rows < wsplit come from W1, else W2 (fuses the Ws/Wa stack).
// EPI=0: plain store to Out. EPI=1: deform-attn proj epilogue
//   cols [0,96):  g_loc[r*96+c]  = v + qpts[r*3 + c%3]
//   cols [96,128): softmax over aligned groups of 4 -> g_attw[r*32 + (c-96)]
template<int EPI>
__global__ __launch_bounds__(256)
void sgemm_nt(const float* __restrict__ A,
              const float* __restrict__ W1, const float* __restrict__ W2, int wsplit,
              const float* __restrict__ b1, const float* __restrict__ b2,
              float* __restrict__ Out, int N,
              const float* __restrict__ qpts)
{
    __shared__ float As[16][68];   // [k][row], row-stride 68 (16B-aligned rows)
    __shared__ float Bs[16][68];   // [k][col]
    const int tid = threadIdx.x;
    const int tx = tid & 15, ty = tid >> 4;
    const int rowBase = blockIdx.y * 64;
    const int colBase = blockIdx.x * 64;
    const int lr = tid >> 2;            // 0..63
    const int lc = (tid & 3) * 4;       // 0,4,8,12

    const float* Aptr = A + (rowBase + lr) * 256 + lc;
    const int wrow = colBase + lr;
    const float* Wptr = (wrow < wsplit) ? (W1 + wrow * 256 + lc)
                                        : (W2 + (wrow - wsplit) * 256 + lc);
    float4 ra = *(const float4*)Aptr;
    float4 rw = *(const float4*)Wptr;

    u64 acc[4][2];
    #pragma unroll
    for (int i = 0; i < 4; i++) { acc[i][0] = 0ull; acc[i][1] = 0ull; }

    for (int kt = 0; kt < 256; kt += 16) {
        As[lc+0][lr] = ra.x; As[lc+1][lr] = ra.y; As[lc+2][lr] = ra.z; As[lc+3][lr] = ra.w;
        Bs[lc+0][lr] = rw.x; Bs[lc+1][lr] = rw.y; Bs[lc+2][lr] = rw.z; Bs[lc+3][lr] = rw.w;
        __syncthreads();
        if (kt < 240) {
            ra = *(const float4*)(Aptr + kt + 16);
            rw = *(const float4*)(Wptr + kt + 16);
        }
        #pragma unroll
        for (int k = 0; k < 16; k++) {
            float4 av = *(const float4*)&As[k][ty * 4];
            float4 bv = *(const float4*)&Bs[k][tx * 4];
            u64 b01 = pk2(bv.x, bv.y), b23 = pk2(bv.z, bv.w);
            u64 a0 = pk2(av.x, av.x), a1 = pk2(av.y, av.y);
            u64 a2 = pk2(av.z, av.z), a3 = pk2(av.w, av.w);
            acc[0][0] = ffma2(a0, b01, acc[0][0]); acc[0][1] = ffma2(a0, b23, acc[0][1]);
            acc[1][0] = ffma2(a1, b01, acc[1][0]); acc[1][1] = ffma2(a1, b23, acc[1][1]);
            acc[2][0] = ffma2(a2, b01, acc[2][0]); acc[2][1] = ffma2(a2, b23, acc[2][1]);
            acc[3][0] = ffma2(a3, b01, acc[3][0]); acc[3][1] = ffma2(a3, b23, acc[3][1]);
        }
        __syncthreads();
    }

    const int c0 = colBase + tx * 4;
    float bias[4];
    #pragma unroll
    for (int j = 0; j < 4; j++) {
        int c = c0 + j;
        bias[j] = (c < wsplit) ? b1[c] : b2[c - wsplit];
    }

    #pragma unroll
    for (int i = 0; i < 4; i++) {
        const int r = rowBase + ty * 4 + i;
        float2 v01 = up2(acc[i][0]);
        float2 v23 = up2(acc[i][1]);
        float v[4] = { v01.x + bias[0], v01.y + bias[1],
                       v23.x + bias[2], v23.y + bias[3] };
        if (EPI == 0) {
            *(float4*)&Out[r * N + c0] = make_float4(v[0], v[1], v[2], v[3]);
        } else {
            if (c0 < 96) {
                #pragma unroll
                for (int j = 0; j < 4; j++) {
                    int c = c0 + j;
                    g_loc[r * 96 + c] = v[j] + qpts[r * 3 + (c % 3)];
                }
            } else {
                // softmax over the thread's aligned group of 4 logits
                float m0 = fmaxf(fmaxf(v[0], v[1]), fmaxf(v[2], v[3]));
                float e0 = __expf(v[0] - m0), e1 = __expf(v[1] - m0);
                float e2 = __expf(v[2] - m0), e3 = __expf(v[3] - m0);
                float inv = 1.0f / (e0 + e1 + e2 + e3);
                int base = r * 32 + (c0 - 96);
                g_attw[base + 0] = e0 * inv;
                g_attw[base + 1] = e1 * inv;
                g_attw[base + 2] = e2 * inv;
                g_attw[base + 3] = e3 * inv;
            }
        }
    }
}

// ---------------- brute-force 1-NN, candidate-split halves ------------------
// 128 blocks = 64 s-blocks x 2 candidate halves. 4 sampling points / thread.
// Candidates staged in smem as SoA (pairs read as broadcast LDS.64);
// distances for 2 candidates at a time via packed f32x2 FMA.
__global__ __launch_bounds__(256)
void knn_kernel(const float* __restrict__ ipts)
{
    __shared__ __align__(16) float xs[2048];
    __shared__ __align__(16) float ys[2048];
    __shared__ __align__(16) float zs[2048];
    __shared__ __align__(16) float wsq[2048];

    const int tid  = threadIdx.x;
    const int sblk = blockIdx.x >> 1;
    const int half = blockIdx.x & 1;
    const int sbase = sblk * 1024;
    const int b = sbase >> 15;                 // 32768 points per batch
    const int cbase = b * LIN + half * 2048;

    for (int i = tid; i < 2048; i += 256) {
        float x = ipts[(cbase + i) * 3 + 0];
        float y = ipts[(cbase + i) * 3 + 1];
        float z = ipts[(cbase + i) * 3 + 2];
        xs[i] = x; ys[i] = y; zs[i] = z;
        wsq[i] = x * x + y * y + z * z;
    }
    __syncthreads();

    int   s[4], bi[4];
    float best[4];
    u64 ax2[4], ay2[4], az2[4];
    #pragma unroll
    for (int k = 0; k < 4; k++) {
        s[k] = sbase + k * 256 + tid;
        float sx = g_loc[3 * s[k] + 0];
        float sy = g_loc[3 * s[k] + 1];
        float sz = g_loc[3 * s[k] + 2];
        float ax = -2.0f * sx, ay = -2.0f * sy, az = -2.0f * sz;
        ax2[k] = pk2(ax, ax); ay2[k] = pk2(ay, ay); az2[k] = pk2(az, az);
        best[k] = 3.4e38f; bi[k] = 0;
    }

    const u64* X = (const u64*)xs;
    const u64* Y = (const u64*)ys;
    const u64* Z = (const u64*)zs;
    const u64* Wv = (const u64*)wsq;

    #pragma unroll 4
    for (int j = 0; j < 1024; j++) {
        u64 xv = X[j], yv = Y[j], zv = Z[j], wv = Wv[j];
        #pragma unroll
        for (int k = 0; k < 4; k++) {
            u64 d2 = ffma2(xv, ax2[k], wv);
            d2 = ffma2(yv, ay2[k], d2);
            d2 = ffma2(zv, az2[k], d2);
            float2 d = up2(d2);
            if (d.x < best[k]) { best[k] = d.x; bi[k] = 2 * j; }     // strict <:
            if (d.y < best[k]) { best[k] = d.y; bi[k] = 2 * j + 1; } // first-min
        }
    }

    #pragma unroll
    for (int k = 0; k < 4; k++) {
        g_bd[half][s[k]] = best[k];
        g_bi[half][s[k]] = half * 2048 + bi[k];
    }
}

// ---------------- combine halves + gather + weighted sum --------------------
// One warp per (b,q,m); lane = d (coalesced 128B gathers from g_value).
__global__ __launch_bounds__(256)
void gather_kernel()
{
    const int g    = (blockIdx.x * 256 + threadIdx.x) >> 5;  // bq*8 + m
    const int lane = threadIdx.x & 31;
    const int m  = g & 7;
    const int bq = g >> 3;
    const int b  = bq >> 10;
    const int base = bq * 32 + m * 4;
    float acc = 0.0f;
    #pragma unroll
    for (int p = 0; p < 4; p++) {
        int sp = base + p;
        float d0 = g_bd[0][sp], d1 = g_bd[1][sp];
        int l = (d0 <= d1) ? g_bi[0][sp] : g_bi[1][sp];  // tie -> lower index (half 0)
        acc += g_attw[sp] * g_value[(b * LIN + l) * CC + m * 32 + lane];
    }
    g_mid[bq * CC + m * 32 + lane] = acc;
}

// ---------------------------------------------------------------------------
extern "C" void kernel_launch(void* const* d_in, const int* in_sizes, int n_in,
                              void* d_out, int out_size) {
    const float* query = (const float*)d_in[0];
    const float* qpts  = (const float*)d_in[1];
    const float* inp   = (const float*)d_in[2];
    const float* ipts  = (const float*)d_in[3];
    const float* Wv    = (const float*)d_in[4];
    const float* bv    = (const float*)d_in[5];
    const float* Ws    = (const float*)d_in[6];
    const float* bs    = (const float*)d_in[7];
    const float* Wa    = (const float*)d_in[8];
    const float* ba    = (const float*)d_in[9];
    const float* Wo    = (const float*)d_in[10];
    const float* bo    = (const float*)d_in[11];
    float* out = (float*)d_out;

    float *p_value, *p_mid;
    cudaGetSymbolAddress((void**)&p_value, g_value);
    cudaGetSymbolAddress((void**)&p_mid,   g_mid);

    const int BIG = 1 << 30;

    // 1) fused sampling-offset + attention projection, epilogue writes loc/attw
    sgemm_nt<1><<<dim3(2, 32), 256>>>(query, Ws, Wa, 96, bs, ba,
                                      nullptr, 128, qpts);
    // 2) brute-force 1-NN (2 candidate halves per point)
    knn_kernel<<<128, 256>>>(ipts);
    // 3) value projection (independent of 1-2)
    sgemm_nt<0><<<dim3(4, 128), 256>>>(inp, Wv, Wv, BIG, bv, bv,
                                       p_value, 256, nullptr);
    // 4) combine + gather + weighted sum
    gather_kernel<<<2048, 256>>>();
    // 5) output projection
    sgemm_nt<0><<<dim3(4, 32), 256>>>(p_mid, Wo, Wo, BIG, bo, bo,
                                      out, 256, nullptr);
}